// round 5
// baseline (speedup 1.0000x reference)
#include <cuda_runtime.h>
#include <cstdint>

// ============================================================================
// W8A8 GEMM (8192x4096x4096) + fp32 dequant + exact GeLU + int8-quantize,
// output stored as FP32.
//
// Round-5: round-4 evidence (rel_err 0.97 ~= all-zero output) says the int8
// inputs are stored in a wider dtype (harness promotes int8 -> int32). We now
// CLASSIFY each big input on-device (int32 / float32 / raw-int8), convert it
// into __device__ int8 scratch, and run the unchanged IMMA GEMM on that.
// Scalars are order-immune (a = min, b = max; alpha 2e-5 < beta 8).
// ============================================================================

#define BM 128
#define BN 128
#define BK 64
#define STAGES 4
#define KDIM 4096
#define NDIM 4096
#define MDIM 8192

#define XCOUNT (MDIM * KDIM)  // 33554432
#define WCOUNT (NDIM * KDIM)  // 16777216

#define TILE_BYTES (BM * BK)                  // 8192 B per A (or B) stage
#define SMEM_BYTES (STAGES * 2 * TILE_BYTES)  // 64 KB

// ---- int8 scratch (device-global: allocation-free) ----
__device__ int8_t g_x8[XCOUNT];
__device__ int8_t g_w8[WCOUNT];
// flags[0]=x not-int32, flags[1]=x not-f32, flags[2]=w not-int32, flags[3]=w not-f32
__device__ int g_flags[4];

// ============================ helper kernels ================================

__global__ void reset_flags_kernel() {
    g_flags[0] = g_flags[1] = g_flags[2] = g_flags[3] = 0;
}

// Reads the first n_words 4-byte words (== element_count bytes: always in
// bounds whatever the true dtype) and records which interpretations fail.
__global__ void classify_kernel(const void* __restrict__ src, int n_words, int flag_base) {
    const int* pi = (const int*)src;
    const float* pf = (const float*)src;
    int viol_i = 0, viol_f = 0;
    for (int i = blockIdx.x * blockDim.x + threadIdx.x; i < n_words;
         i += gridDim.x * blockDim.x) {
        int v = pi[i];
        if ((unsigned)(v + 127) > 254u) viol_i = 1;
        float f = pf[i];
        if (!(fabsf(f) <= 127.0f && rintf(f) == f)) viol_f = 1;
    }
    unsigned bi = __ballot_sync(0xFFFFFFFFu, viol_i);
    unsigned bf = __ballot_sync(0xFFFFFFFFu, viol_f);
    if ((threadIdx.x & 31) == 0) {
        if (bi) atomicOr(&g_flags[flag_base + 0], 1);
        if (bf) atomicOr(&g_flags[flag_base + 1], 1);
    }
}

// Convert n elements of src (dtype per flags) into packed int8 dst.
__global__ void convert_kernel(const void* __restrict__ src, int8_t* __restrict__ dst, int n,
                               int flag_base) {
    const int not_i32 = g_flags[flag_base + 0];
    const int not_f32 = g_flags[flag_base + 1];
    const int mode = not_i32 ? (not_f32 ? 2 : 1) : 0;  // 0=int32, 1=f32, 2=raw int8
    const int nw = n >> 2;
    unsigned* dw = (unsigned*)dst;
    for (int i = blockIdx.x * blockDim.x + threadIdx.x; i < nw; i += gridDim.x * blockDim.x) {
        unsigned w;
        if (mode == 0) {
            int4 v = ((const int4*)src)[i];
            w = (v.x & 0xFF) | ((v.y & 0xFF) << 8) | ((v.z & 0xFF) << 16) | ((v.w & 0xFF) << 24);
        } else if (mode == 1) {
            float4 f = ((const float4*)src)[i];
            int x0 = (int)rintf(f.x), x1 = (int)rintf(f.y);
            int x2 = (int)rintf(f.z), x3 = (int)rintf(f.w);
            w = (x0 & 0xFF) | ((x1 & 0xFF) << 8) | ((x2 & 0xFF) << 16) | ((x3 & 0xFF) << 24);
        } else {
            w = ((const unsigned*)src)[i];
        }
        dw[i] = w;
    }
}

// ============================ GEMM (unchanged core) =========================

__device__ __forceinline__ void cp16(void* smem_ptr, const void* gmem_ptr) {
    uint32_t s = (uint32_t)__cvta_generic_to_shared(smem_ptr);
    asm volatile("cp.async.cg.shared.global [%0], [%1], 16;\n" ::"r"(s), "l"(gmem_ptr));
}
__device__ __forceinline__ void cp_commit() {
    asm volatile("cp.async.commit_group;\n");
}
__device__ __forceinline__ void cp_wait2() {
    asm volatile("cp.async.wait_group 2;\n");
}

__device__ __forceinline__ void ldsm4(uint32_t& r0, uint32_t& r1, uint32_t& r2, uint32_t& r3,
                                      const void* p) {
    uint32_t s = (uint32_t)__cvta_generic_to_shared(p);
    asm volatile("ldmatrix.sync.aligned.m8n8.x4.shared.b16 {%0,%1,%2,%3}, [%4];\n"
                 : "=r"(r0), "=r"(r1), "=r"(r2), "=r"(r3)
                 : "r"(s));
}

__device__ __forceinline__ void mma_s8(int* c, uint32_t a0, uint32_t a1, uint32_t a2, uint32_t a3,
                                       uint32_t b0, uint32_t b1) {
    asm volatile(
        "mma.sync.aligned.m16n8k32.row.col.s32.s8.s8.s32 "
        "{%0,%1,%2,%3}, {%4,%5,%6,%7}, {%8,%9}, {%0,%1,%2,%3};\n"
        : "+r"(c[0]), "+r"(c[1]), "+r"(c[2]), "+r"(c[3])
        : "r"(a0), "r"(a1), "r"(a2), "r"(a3), "r"(b0), "r"(b1));
}

// dequant + exact GeLU + quantize-to-int8 range, returned AS FLOAT.
__device__ __forceinline__ float quant_gelu_f(int acc, float bias_v, float a, float b) {
    float v = fmaf(a, (float)acc, bias_v);
    float g = 0.5f * v * (1.0f + erff(v * 0.70710678118654752440f));
    float q = nearbyintf(g * b);
    q = fminf(fmaxf(q, -128.0f), 127.0f);
    return q;
}

extern __shared__ int8_t smem_dyn[];

__global__ void __launch_bounds__(256, 2)
w8a8_gelu_q_kernel(const float* __restrict__ bias, const float* __restrict__ s0_ptr,
                   const float* __restrict__ s1_ptr, float* __restrict__ out) {
    const int8_t* __restrict__ X = g_x8;
    const int8_t* __restrict__ W = g_w8;

    const int tid = threadIdx.x;
    const int warp = tid >> 5;
    const int lane = tid & 31;
    const int bn = blockIdx.x;  // N block (0..31)
    const int bm = blockIdx.y;  // M block (0..63)

    const int wm = warp & 1;   // 2 warps along M (64 rows each)
    const int wn = warp >> 1;  // 4 warps along N (32 cols each)

    int8_t* sA = smem_dyn;                        // STAGES * 8192
    int8_t* sB = smem_dyn + STAGES * TILE_BYTES;  // STAGES * 8192

    auto load_stage = [&](int s, int k0) {
#pragma unroll
        for (int i = 0; i < 2; ++i) {
            int id = tid + i * 256;
            int row = id >> 2;
            int c = id & 3;
            int sw = c ^ ((row >> 1) & 3);
            cp16(sA + s * TILE_BYTES + row * 64 + sw * 16,
                 X + (size_t)(bm * BM + row) * KDIM + k0 + c * 16);
            cp16(sB + s * TILE_BYTES + row * 64 + sw * 16,
                 W + (size_t)(bn * BN + row) * KDIM + k0 + c * 16);
        }
    };

    int acc[4][4][4];
#pragma unroll
    for (int mi = 0; mi < 4; ++mi)
#pragma unroll
        for (int ni = 0; ni < 4; ++ni)
#pragma unroll
            for (int j = 0; j < 4; ++j) acc[mi][ni][j] = 0;

    const int KTILES = KDIM / BK;  // 64

#pragma unroll
    for (int s = 0; s < STAGES - 1; ++s) {
        load_stage(s, s * BK);
        cp_commit();
    }

    for (int kt = 0; kt < KTILES; ++kt) {
        cp_wait2();
        __syncthreads();

        if (kt + STAGES - 1 < KTILES) load_stage((kt + STAGES - 1) % STAGES, (kt + STAGES - 1) * BK);
        cp_commit();

        const int8_t* sAs = sA + (kt % STAGES) * TILE_BYTES;
        const int8_t* sBs = sB + (kt % STAGES) * TILE_BYTES;

#pragma unroll
        for (int ks = 0; ks < 2; ++ks) {  // two k32 steps per BK=64
            uint32_t bfrag[4][2];
#pragma unroll
            for (int h = 0; h < 2; ++h) {
                int rl = (lane & 7) + ((lane >> 4) << 3);
                int rB = wn * 32 + h * 16 + rl;
                int c = ks * 2 + ((lane >> 3) & 1);
                int sw = c ^ ((rB >> 1) & 3);
                ldsm4(bfrag[h * 2][0], bfrag[h * 2][1], bfrag[h * 2 + 1][0], bfrag[h * 2 + 1][1],
                      sBs + rB * 64 + sw * 16);
            }
#pragma unroll
            for (int mi = 0; mi < 4; ++mi) {
                int rA = wm * 64 + mi * 16 + (lane & 15);
                int c = ks * 2 + (lane >> 4);
                int sw = c ^ ((rA >> 1) & 3);
                uint32_t a0, a1, a2, a3;
                ldsm4(a0, a1, a2, a3, sAs + rA * 64 + sw * 16);
#pragma unroll
                for (int ni = 0; ni < 4; ++ni)
                    mma_s8(acc[mi][ni], a0, a1, a2, a3, bfrag[ni][0], bfrag[ni][1]);
            }
        }
    }

    // ---- epilogue: dequant + exact GeLU + quantize, stored as FP32 ----
    const float s0 = __ldg(s0_ptr);
    const float s1 = __ldg(s1_ptr);
    const float a = fminf(s0, s1);  // alpha = 2e-5
    const float b = fmaxf(s0, s1);  // beta  = 8.0

    float2 bias2[4];
#pragma unroll
    for (int ni = 0; ni < 4; ++ni) {
        int col = bn * BN + wn * 32 + ni * 8 + ((lane & 3) << 1);
        bias2[ni] = *(const float2*)(bias + col);
    }

#pragma unroll
    for (int mi = 0; mi < 4; ++mi) {
        int row = bm * BM + wm * 64 + mi * 16 + (lane >> 2);
#pragma unroll
        for (int ni = 0; ni < 4; ++ni) {
            int col = bn * BN + wn * 32 + ni * 8 + ((lane & 3) << 1);
            float2 p0, p1;
            p0.x = quant_gelu_f(acc[mi][ni][0], bias2[ni].x, a, b);
            p0.y = quant_gelu_f(acc[mi][ni][1], bias2[ni].y, a, b);
            p1.x = quant_gelu_f(acc[mi][ni][2], bias2[ni].x, a, b);
            p1.y = quant_gelu_f(acc[mi][ni][3], bias2[ni].y, a, b);
            *(float2*)(out + (size_t)row * NDIM + col) = p0;
            *(float2*)(out + (size_t)(row + 8) * NDIM + col) = p1;
        }
    }
}

// ============================== launcher ====================================

extern "C" void kernel_launch(void* const* d_in, const int* in_sizes, int n_in,
                              void* d_out, int out_size) {
    // Resolve inputs BY SIZE (element OR byte counts):
    //   x: 33554432 elems (or *4 bytes), weight: 16777216 (or *4),
    //   bias: 4096 / 16384, scalars: 1 / 4.
    const void* X = nullptr;
    const void* W = nullptr;
    const float* bias = nullptr;
    const float* s0 = nullptr;
    const float* s1 = nullptr;
    for (int i = 0; i < n_in; ++i) {
        long long sz = in_sizes[i];
        if (sz == (long long)XCOUNT || sz == (long long)XCOUNT * 4) X = d_in[i];
        else if (sz == (long long)WCOUNT || sz == (long long)WCOUNT * 4) W = d_in[i];
        else if (sz == NDIM || sz == NDIM * 4) bias = (const float*)d_in[i];
        else if (sz == 1 || sz == 4) {
            if (!s0) s0 = (const float*)d_in[i];
            else if (!s1) s1 = (const float*)d_in[i];
        }
    }
    if (!X || !W || !bias || !s0 || !s1) return;  // leave output poisoned: clean failure signal
    float* out = (float*)d_out;

    // 1) classify input dtypes (reads only element_count bytes: always in-bounds)
    reset_flags_kernel<<<1, 1>>>();
    classify_kernel<<<2048, 256>>>(X, XCOUNT / 4, 0);
    classify_kernel<<<2048, 256>>>(W, WCOUNT / 4, 2);
    // 2) convert to packed int8 scratch
    int8_t* x8;
    int8_t* w8;
    cudaGetSymbolAddress((void**)&x8, g_x8);
    cudaGetSymbolAddress((void**)&w8, g_w8);
    convert_kernel<<<4096, 256>>>(X, x8, XCOUNT, 0);
    convert_kernel<<<4096, 256>>>(W, w8, WCOUNT, 2);

    // 3) IMMA GEMM + fused epilogue
    cudaFuncSetAttribute(w8a8_gelu_q_kernel, cudaFuncAttributeMaxDynamicSharedMemorySize,
                         SMEM_BYTES);
    dim3 grid(NDIM / BN, MDIM / BM);  // (32, 64)
    w8a8_gelu_q_kernel<<<grid, 256, SMEM_BYTES>>>(bias, s0, s1, out);
}